// round 15
// baseline (speedup 1.0000x reference)
#include <cuda_runtime.h>
#include <cuda_fp16.h>
#include <math.h>
#include <stdint.h>

// ---------------------------------------------------------------------------
// SubSample attention block — fp16 mma.sync (m16n8k16), position-major.
// Round 15: round-12/14 base + (a) coalesced fc2 TRANS epilogue via
// transposed smem bounce, (b) prep+xtrans merged into one launch.
// ---------------------------------------------------------------------------

constexpr int BATCH = 32, CIN = 256, NP = 1024, QP = 256;
constexpr int HEADS = 8, KD = 32, VD = 128;
constexpr int KVC = (KD + VD) * HEADS;   // 1280
constexpr int QC  = HEADS * KD;          // 256
constexpr int MERGE = HEADS * VD;        // 1024
constexpr int DOUT = 512, HID = 1024;

constexpr int HS_STAGE = 128 * 72;                 // halves per operand-stage
constexpr int GH_SMEM_BYTES = 4 * HS_STAGE * 2;    // 73728

constexpr int FL_QS = 128 * 40;
constexpr int FL_KS = 128 * 40;
constexpr int FL_VS = 128 * 136;
constexpr int FL_SMEM_BYTES = (FL_QS + 2 * FL_KS + 2 * FL_VS) * 2;  // 100352

__device__ __align__(16) __half g_x16T [(size_t)BATCH * NP * CIN];
__device__ __align__(16) __half g_xq16T[(size_t)BATCH * QP * CIN];
__device__ __align__(16) __half g_kv16 [(size_t)BATCH * NP * KVC];
__device__ __align__(16) __half g_q16  [(size_t)BATCH * QP * QC];
__device__ __align__(16) __half g_oT16 [(size_t)BATCH * QP * MERGE];
__device__ __align__(16) __half g_mg16 [(size_t)BATCH * QP * DOUT];
__device__ __align__(16) __half g_f116 [(size_t)BATCH * QP * HID];
__device__ __align__(16) __half g_kvw16 [KVC * CIN];
__device__ __align__(16) __half g_qw16  [QC * CIN];
__device__ __align__(16) __half g_mgw16 [DOUT * MERGE];
__device__ __align__(16) __half g_fc1w16[HID * DOUT];
__device__ __align__(16) __half g_fc2w16[DOUT * HID];
__device__ float g_sc[3584];
__device__ float g_bi[3584];

__device__ __forceinline__ float gelu_exact(float x) {
    return 0.5f * x * (1.0f + erff(x * 0.70710678118654752f));
}

__device__ __forceinline__ void cpa16(void* dst, const void* src) {
    unsigned d = (unsigned)__cvta_generic_to_shared(dst);
    asm volatile("cp.async.ca.shared.global [%0], [%1], 16;\n" :: "r"(d), "l"(src));
}
__device__ __forceinline__ void cp_commit() { asm volatile("cp.async.commit_group;\n"); }
template <int W> __device__ __forceinline__ void cp_wait() {
    asm volatile("cp.async.wait_group %0;\n" :: "n"(W));
}

__device__ __forceinline__ void mma_f16(float* c, const unsigned* a, unsigned b0, unsigned b1) {
    asm volatile(
        "mma.sync.aligned.m16n8k16.row.col.f32.f16.f16.f32 "
        "{%0,%1,%2,%3}, {%4,%5,%6,%7}, {%8,%9}, {%0,%1,%2,%3};"
        : "+f"(c[0]), "+f"(c[1]), "+f"(c[2]), "+f"(c[3])
        : "r"(a[0]), "r"(a[1]), "r"(a[2]), "r"(a[3]), "r"(b0), "r"(b1));
}

__device__ __forceinline__ void ldsm4(unsigned& r0, unsigned& r1, unsigned& r2,
                                      unsigned& r3, unsigned addr) {
    asm volatile("ldmatrix.sync.aligned.m8n8.x4.shared.b16 {%0,%1,%2,%3}, [%4];"
                 : "=r"(r0), "=r"(r1), "=r"(r2), "=r"(r3) : "r"(addr));
}
__device__ __forceinline__ void ldsm_t4(unsigned& r0, unsigned& r1, unsigned& r2,
                                        unsigned& r3, unsigned addr) {
    asm volatile("ldmatrix.sync.aligned.m8n8.x4.trans.shared.b16 {%0,%1,%2,%3}, [%4];"
                 : "=r"(r0), "=r"(r1), "=r"(r2), "=r"(r3) : "r"(addr));
}

__device__ __forceinline__ unsigned packh2(float a, float b) {
    __half2 h = __floats2half2_rn(a, b);
    return *reinterpret_cast<unsigned*>(&h);
}
__device__ __forceinline__ unsigned ldu32(const __half* p) {
    return *reinterpret_cast<const unsigned*>(p);
}
__device__ __forceinline__ unsigned s2u32(const void* p) {
    unsigned a;
    asm("{ .reg .u64 tmp; cvta.to.shared.u64 tmp, %1; cvt.u32.u64 %0, tmp; }"
        : "=r"(a) : "l"(p));
    return a;
}

// ---------------------------------------------------------------------------
// merged prologue + transpose: blocks [0,8192) transpose x; [8192,8206) fold
// BN; [8206,...) convert weights. All parts independent.
// ---------------------------------------------------------------------------
struct PrepArgs {
    const float *g[5], *b[5], *m[5], *v[5];
    const float* wsrc[5];
    __half* wdst[5];
    int wn[5];
    float qmul;
};
__global__ void prep_trans(PrepArgs pa, float* __restrict__ sc, float* __restrict__ bi,
                           const float* __restrict__ x, __half* __restrict__ xT,
                           __half* __restrict__ xqT) {
    __shared__ float tile[32][33];
    const int bid = blockIdx.x;
    const int t = threadIdx.x;
    if (bid < 8192) {
        // x [b][256][1024] f32 -> xT [b][1024][256] f16 (+ xqT subsample)
        int bxx = bid & 31;
        int byy = (bid >> 5) & 7;
        int bz  = bid >> 8;
        int tx = t & 31, ty = t >> 5;
        int hw0 = bxx * 32, c0 = byy * 32;
#pragma unroll
        for (int j = 0; j < 4; j++)
            tile[ty + 8 * j][tx] =
                x[((size_t)(bz * CIN + c0 + ty + 8 * j) << 10) + hw0 + tx];
        __syncthreads();
        const bool evenrow = (bxx & 1) == 0;
#pragma unroll
        for (int j = 0; j < 4; j++) {
            int hwl = ty + 8 * j;
            __half v = __float2half_rn(tile[tx][hwl]);
            xT[((size_t)bz * NP + hw0 + hwl) * CIN + c0 + tx] = v;
            if (evenrow && !(hwl & 1)) {
                int qp = (bxx >> 1) * 16 + (hwl >> 1);
                xqT[((size_t)bz * QP + qp) * CIN + c0 + tx] = v;
            }
        }
        return;
    }
    if (bid < 8206) {
        int i = (bid - 8192) * 256 + t;
        if (i >= 3584) return;
        int seg, off;
        float mul = 1.0f;
        if (i < 1280)      { seg = 0; off = 0; }
        else if (i < 1536) { seg = 1; off = 1280; mul = pa.qmul; }
        else if (i < 2048) { seg = 2; off = 1536; }
        else if (i < 3072) { seg = 3; off = 2048; }
        else               { seg = 4; off = 3072; }
        int j = i - off;
        float s = pa.g[seg][j] * rsqrtf(pa.v[seg][j] + 1e-5f);
        sc[i] = s * mul;
        bi[i] = (pa.b[seg][j] - pa.m[seg][j] * s) * mul;
        return;
    }
    int i = (bid - 8206) * 256 + t;
#pragma unroll
    for (int s = 0; s < 5; s++) {
        if (i < pa.wn[s]) { pa.wdst[s][i] = __float2half_rn(pa.wsrc[s][i]); return; }
        i -= pa.wn[s];
    }
}

// ---------------------------------------------------------------------------
// fp16 GEMM core: BK=64, 2-stage cp.async, ldmatrix fragments.
// TRANS epilogue: transposed smem bounce [n][136] -> coalesced f32 row stores.
// ---------------------------------------------------------------------------
template <bool GEL, bool TRANS>
__device__ __forceinline__
void gemm_core(const __half* __restrict__ Abase, const __half* __restrict__ Bbase,
               void* __restrict__ Cv, int K, int ldc, int bm, int bn,
               const float* __restrict__ scale, const float* __restrict__ bias,
               __half* smh) {
    __half* As = smh;                    // [2][128*72]
    __half* Bs = smh + 2 * HS_STAGE;     // [2][128*72]

    const int t = threadIdx.x, warp = t >> 5, lane = t & 31;
    const int wm = warp & 1, wn = warp >> 1;
    const int g = lane >> 2, tq = lane & 3;

    const __half* Ab = Abase + (long long)bm * K;
    const __half* Bb = Bbase + (long long)bn * K;

    const int arow = ((lane >> 3) & 1) * 8 + (lane & 7);
    const int akadd = (lane >> 4) * 8;
    const int brow = (lane >> 4) * 8 + (lane & 7);
    const int bkadd = ((lane >> 3) & 1) * 8;
    const unsigned as_u32 = s2u32(As);
    const unsigned bs_u32 = s2u32(Bs);

    auto ldtile = [&](int s, int k0) {
#pragma unroll
        for (int j = 0; j < 4; j++) {
            int idx = j * 256 + t;
            int r = idx >> 3, c = idx & 7;
            cpa16(As + s * HS_STAGE + r * 72 + c * 8, Ab + (long long)r * K + k0 + c * 8);
            cpa16(Bs + s * HS_STAGE + r * 72 + c * 8, Bb + (long long)r * K + k0 + c * 8);
        }
    };

    float acc[4][4][4];
#pragma unroll
    for (int i = 0; i < 4; i++)
#pragma unroll
        for (int j = 0; j < 4; j++)
#pragma unroll
            for (int r = 0; r < 4; r++) acc[i][j][r] = 0.0f;

    const int niter = K >> 6;
    ldtile(0, 0);
    cp_commit();

    for (int it = 0; it < niter; it++) {
        const int s = it & 1;
        if (it + 1 < niter) ldtile(s ^ 1, (it + 1) << 6);
        cp_commit();
        cp_wait<1>();
        __syncthreads();

        const unsigned as0 = as_u32 + (unsigned)(s * HS_STAGE * 2);
        const unsigned bs0 = bs_u32 + (unsigned)(s * HS_STAGE * 2);
#pragma unroll
        for (int kb = 0; kb < 4; kb++) {
            const int ko = kb * 16;
            unsigned a[4][4];
#pragma unroll
            for (int mi = 0; mi < 4; mi++)
                ldsm4(a[mi][0], a[mi][1], a[mi][2], a[mi][3],
                      as0 + 2u * (unsigned)((wm * 64 + mi * 16 + arow) * 72 + ko + akadd));
            unsigned b[4][2];
#pragma unroll
            for (int nip = 0; nip < 2; nip++)
                ldsm4(b[2 * nip][0], b[2 * nip][1], b[2 * nip + 1][0], b[2 * nip + 1][1],
                      bs0 + 2u * (unsigned)((wn * 32 + nip * 16 + brow) * 72 + ko + bkadd));
#pragma unroll
            for (int mi = 0; mi < 4; mi++)
#pragma unroll
                for (int ni = 0; ni < 4; ni++)
                    mma_f16(acc[mi][ni], a[mi], b[ni][0], b[ni][1]);
        }
        __syncthreads();
    }

    if (!TRANS) {
        __half* Cb = reinterpret_cast<__half*>(Cv);
#pragma unroll
        for (int mi = 0; mi < 4; mi++) {
            int r0 = bm + wm * 64 + mi * 16 + g;
            int r1 = r0 + 8;
#pragma unroll
            for (int ni = 0; ni < 4; ni++) {
                int col = bn + wn * 32 + ni * 8 + 2 * tq;
                float s0 = scale[col], b0s = bias[col];
                float s1 = scale[col + 1], b1s = bias[col + 1];
                float v0 = fmaf(acc[mi][ni][0], s0, b0s);
                float v1 = fmaf(acc[mi][ni][1], s1, b1s);
                float v2 = fmaf(acc[mi][ni][2], s0, b0s);
                float v3 = fmaf(acc[mi][ni][3], s1, b1s);
                if (GEL) {
                    v0 = gelu_exact(v0); v1 = gelu_exact(v1);
                    v2 = gelu_exact(v2); v3 = gelu_exact(v3);
                }
                *reinterpret_cast<unsigned*>(Cb + (long long)r0 * ldc + col) = packh2(v0, v1);
                *reinterpret_cast<unsigned*>(Cb + (long long)r1 * ldc + col) = packh2(v2, v3);
            }
        }
    } else {
        // transposed bounce: Cs[n(128)][136] floats = 69632 B (fits in tile smem)
        float* Cs = reinterpret_cast<float*>(smh);
        __syncthreads();
#pragma unroll
        for (int mi = 0; mi < 4; mi++) {
            int r0 = wm * 64 + mi * 16 + g;
            int r1 = r0 + 8;
#pragma unroll
            for (int ni = 0; ni < 4; ni++) {
                int col = wn * 32 + ni * 8 + 2 * tq;
                int cg = bn + col;
                float s0 = scale[cg], b0s = bias[cg];
                float s1 = scale[cg + 1], b1s = bias[cg + 1];
                Cs[col * 136 + r0]       = fmaf(acc[mi][ni][0], s0, b0s);
                Cs[(col + 1) * 136 + r0] = fmaf(acc[mi][ni][1], s1, b1s);
                Cs[col * 136 + r1]       = fmaf(acc[mi][ni][2], s0, b0s);
                Cs[(col + 1) * 136 + r1] = fmaf(acc[mi][ni][3], s1, b1s);
            }
        }
        __syncthreads();
        float* Cb = reinterpret_cast<float*>(Cv);
#pragma unroll
        for (int i = 0; i < 16; i++) {
            int idx = i * 256 + t;
            int n = idx >> 5;            // 0..127 (warp-uniform)
            int m = (idx & 31) * 4;      // lane*4 -> coalesced row store
            float4 v = *reinterpret_cast<const float4*>(Cs + n * 136 + m);
            *reinterpret_cast<float4*>(Cb + (long long)(bn + n) * ldc + bm + m) = v;
        }
    }
}

// generic single-GEMM wrapper
template <bool GEL, bool TRANS>
__global__ __launch_bounds__(256, 2)
void gemm_h(const __half* __restrict__ A, const __half* __restrict__ B,
            void* __restrict__ Cv,
            int K, int ldc, long long sA, long long sC,
            const float* __restrict__ scale, const float* __restrict__ bias) {
    extern __shared__ __half smh[];
    const __half* Az = A + (long long)blockIdx.z * sA;
    char* Cz = reinterpret_cast<char*>(Cv) +
               (long long)blockIdx.z * sC * (TRANS ? 4 : 2);
    gemm_core<GEL, TRANS>(Az, B, Cz, K, ldc,
                          blockIdx.y * 128, blockIdx.x * 128, scale, bias, smh);
}

// fused kv + q wrapper: grid (10, 9, 32). y<8 -> kv tile; y==8, x<4 -> q tile.
__global__ __launch_bounds__(256, 2)
void gemm_kvq(const __half* __restrict__ xT, const __half* __restrict__ kvw,
              __half* __restrict__ kv,
              const __half* __restrict__ xqT, const __half* __restrict__ qw,
              __half* __restrict__ qo,
              const float* __restrict__ sc, const float* __restrict__ bi) {
    extern __shared__ __half smh[];
    const int z = blockIdx.z;
    if (blockIdx.y < 8) {
        gemm_core<false, false>(xT + (long long)z * NP * CIN, kvw,
                                kv + (long long)z * NP * KVC,
                                CIN, KVC, blockIdx.y * 128, blockIdx.x * 128,
                                sc + 0, bi + 0, smh);
    } else {
        if (blockIdx.x >= 4) return;
        const int qm = blockIdx.x >> 1, qn = blockIdx.x & 1;
        gemm_core<false, false>(xqT + (long long)z * QP * CIN, qw,
                                qo + (long long)z * QP * QC,
                                CIN, QC, qm * 128, qn * 128,
                                sc + 1280, bi + 1280, smh);
    }
}

// ---------------------------------------------------------------------------
// Flash attention fp16, 128-key blocks, exp2-domain softmax (round-12).
// ---------------------------------------------------------------------------
__global__ __launch_bounds__(256, 1)
void flash_attn(const __half* __restrict__ q, const __half* __restrict__ kv,
                __half* __restrict__ oT) {
    const int t    = threadIdx.x;
    const int warp = t >> 5, lane = t & 31;
    const int g    = lane >> 2, tq = lane & 3;
    const int bh   = blockIdx.y;
    const int b    = bh >> 3, h = bh & 7;
    const int q0   = blockIdx.x * 128;

    extern __shared__ __half smh[];
    __half* Qs = smh;               // [128 qp][40]
    __half* Ks = Qs + FL_QS;        // [2][128 n][40]
    __half* Vs = Ks + 2 * FL_KS;    // [2][128 n][136]

    const __half* kvb = kv + (size_t)b * NP * KVC + h * (KD + VD);

    auto loadKV = [&](int s, int n0) {
        __half* ks = Ks + s * FL_KS;
#pragma unroll
        for (int j = 0; j < 2; j++) {
            int idx = j * 256 + t;
            int n = idx >> 2, c = idx & 3;
            cpa16(ks + n * 40 + c * 8, kvb + (size_t)(n0 + n) * KVC + c * 8);
        }
        __half* vs = Vs + s * FL_VS;
#pragma unroll
        for (int j = 0; j < 8; j++) {
            int idx = j * 256 + t;
            int n = idx >> 4, c = idx & 15;
            cpa16(vs + n * 136 + c * 8, kvb + (size_t)(n0 + n) * KVC + KD + c * 8);
        }
    };

#pragma unroll
    for (int j = 0; j < 2; j++) {
        int idx = j * 256 + t;
        int r = idx >> 2, c = idx & 3;
        cpa16(Qs + r * 40 + c * 8, q + ((size_t)b * QP + q0 + r) * QC + h * KD + c * 8);
    }
    loadKV(0, 0);
    cp_commit();

    unsigned aq[2][4];
    float m0 = -1e30f, m1 = -1e30f, l0 = 0.0f, l1 = 0.0f;
    float o[16][4];
#pragma unroll
    for (int j = 0; j < 16; j++)
#pragma unroll
        for (int r = 0; r < 4; r++) o[j][r] = 0.0f;

    const int brow = (lane >> 4) * 8 + (lane & 7);
    const int bkadd = ((lane >> 3) & 1) * 8;
    const int lmi = lane >> 3, lrow = lane & 7;
    const int ldrow = ((lmi & 1) * 8 + lrow) * 136 + (lmi >> 1) * 8;

    for (int blk = 0; blk < 8; blk++) {
        const int s = blk & 1;
        if (blk + 1 < 8) loadKV(s ^ 1, (blk + 1) * 128);
        cp_commit();
        cp_wait<1>();
        __syncthreads();

        if (blk == 0) {
#pragma unroll
            for (int kb = 0; kb < 2; kb++) {
                int r = warp * 16 + g;
                aq[kb][0] = ldu32(Qs + r * 40 + kb * 16 + 2 * tq);
                aq[kb][1] = ldu32(Qs + (r + 8) * 40 + kb * 16 + 2 * tq);
                aq[kb][2] = ldu32(Qs + r * 40 + kb * 16 + 2 * tq + 8);
                aq[kb][3] = ldu32(Qs + (r + 8) * 40 + kb * 16 + 2 * tq + 8);
            }
        }

        const unsigned ks_u32 = s2u32(Ks + s * FL_KS);
        const unsigned vs_u32 = s2u32(Vs + s * FL_VS);

        float p[16][4];
#pragma unroll
        for (int ni = 0; ni < 16; ni++)
            p[ni][0] = p[ni][1] = p[ni][2] = p[ni][3] = 0.0f;
#pragma unroll
        for (int kb = 0; kb < 2; kb++) {
#pragma unroll
            for (int nip = 0; nip < 8; nip++) {
                unsigned b00, b01, b10, b11;
                ldsm4(b00, b01, b10, b11,
                      ks_u32 + 2u * (unsigned)((nip * 16 + brow) * 40 + kb * 16 + bkadd));
                mma_f16(p[2 * nip],     aq[kb], b00, b01);
                mma_f16(p[2 * nip + 1], aq[kb], b10, b11);
            }
        }

        float bm0 = -1e30f, bm1 = -1e30f;
#pragma unroll
        for (int ni = 0; ni < 16; ni++) {
            bm0 = fmaxf(bm0, fmaxf(p[ni][0], p[ni][1]));
            bm1 = fmaxf(bm1, fmaxf(p[ni][2], p[ni][3]));
        }
        bm0 = fmaxf(bm0, __shfl_xor_sync(0xffffffffu, bm0, 1));
        bm0 = fmaxf(bm0, __shfl_xor_sync(0xffffffffu, bm0, 2));
        bm1 = fmaxf(bm1, __shfl_xor_sync(0xffffffffu, bm1, 1));
        bm1 = fmaxf(bm1, __shfl_xor_sync(0xffffffffu, bm1, 2));
        float mn0 = fmaxf(m0, bm0), mn1 = fmaxf(m1, bm1);
        float al0 = exp2f(m0 - mn0), al1 = exp2f(m1 - mn1);
        float rs0 = 0.0f, rs1 = 0.0f;
#pragma unroll
        for (int ni = 0; ni < 16; ni++) {
            p[ni][0] = exp2f(p[ni][0] - mn0);
            p[ni][1] = exp2f(p[ni][1] - mn0);
            p[ni][2] = exp2f(p[ni][2] - mn1);
            p[ni][3] = exp2f(p[ni][3] - mn1);
            rs0 += p[ni][0] + p[ni][1];
            rs1 += p[ni][2] + p[ni][3];
        }
        rs0 += __shfl_xor_sync(0xffffffffu, rs0, 1);
        rs0 += __shfl_xor_sync(0xffffffffu, rs0, 2);
        rs1 += __shfl_xor_sync(0xffffffffu, rs1, 1);
        rs1 += __shfl_xor_sync(0xffffffffu, rs1, 2);
        l0 = l0 * al0 + rs0;
        l1 = l1 * al1 + rs1;
        m0 = mn0; m1 = mn1;
#pragma unroll
        for (int j = 0; j < 16; j++) {
            o[j][0] *= al0; o[j][1] *= al0;
            o[j][2] *= al1; o[j][3] *= al1;
        }

#pragma unroll
        for (int ki = 0; ki < 8; ki++) {
            unsigned ap[4];
            ap[0] = packh2(p[2 * ki][0],     p[2 * ki][1]);
            ap[1] = packh2(p[2 * ki][2],     p[2 * ki][3]);
            ap[2] = packh2(p[2 * ki + 1][0], p[2 * ki + 1][1]);
            ap[3] = packh2(p[2 * ki + 1][2], p[2 * ki + 1][3]);
#pragma unroll
            for (int jj = 0; jj < 8; jj++) {
                unsigned r0, r1, r2, r3;
                ldsm_t4(r0, r1, r2, r3,
                        vs_u32 + 2u * (unsigned)(ki * 16 * 136 + jj * 16 + ldrow));
                mma_f16(o[2 * jj],     ap, r0, r1);
                mma_f16(o[2 * jj + 1], ap, r2, r3);
            }
        }
        __syncthreads();
    }

    float inv0 = 1.0f / l0, inv1 = 1.0f / l1;
    int r0 = q0 + warp * 16 + g;
    int r1 = r0 + 8;
    __half* orow0 = oT + ((size_t)b * QP + r0) * MERGE + h * VD;
    __half* orow1 = oT + ((size_t)b * QP + r1) * MERGE + h * VD;
#pragma unroll
    for (int j = 0; j < 16; j++) {
        int col = j * 8 + 2 * tq;
        float v0 = gelu_exact(o[j][0] * inv0);
        float v1 = gelu_exact(o[j][1] * inv0);
        float v2 = gelu_exact(o[j][2] * inv1);
        float v3 = gelu_exact(o[j][3] * inv1);
        *reinterpret_cast<unsigned*>(orow0 + col) = packh2(v0, v1);
        *reinterpret_cast<unsigned*>(orow1 + col) = packh2(v2, v3);
    }
}

// ---------------------------------------------------------------------------
extern "C" void kernel_launch(void* const* d_in, const int* in_sizes, int n_in,
                              void* d_out, int out_size) {
    const float* x     = (const float*)d_in[0];
    const float* kv_w  = (const float*)d_in[1];
    const float* q_w   = (const float*)d_in[6];
    const float* mg_w  = (const float*)d_in[11];
    const float* fc1_w = (const float*)d_in[16];
    const float* fc2_w = (const float*)d_in[21];
    float* out = (float*)d_out;

    __half *xT, *xqT, *kv, *q, *oT, *mg, *f1;
    __half *kvw, *qw, *mgw, *fc1w, *fc2w;
    float *sc, *bi;
    cudaGetSymbolAddress((void**)&xT,   g_x16T);
    cudaGetSymbolAddress((void**)&xqT,  g_xq16T);
    cudaGetSymbolAddress((void**)&kv,   g_kv16);
    cudaGetSymbolAddress((void**)&q,    g_q16);
    cudaGetSymbolAddress((void**)&oT,   g_oT16);
    cudaGetSymbolAddress((void**)&mg,   g_mg16);
    cudaGetSymbolAddress((void**)&f1,   g_f116);
    cudaGetSymbolAddress((void**)&kvw,  g_kvw16);
    cudaGetSymbolAddress((void**)&qw,   g_qw16);
    cudaGetSymbolAddress((void**)&mgw,  g_mgw16);
    cudaGetSymbolAddress((void**)&fc1w, g_fc1w16);
    cudaGetSymbolAddress((void**)&fc2w, g_fc2w16);
    cudaGetSymbolAddress((void**)&sc,   g_sc);
    cudaGetSymbolAddress((void**)&bi,   g_bi);

    cudaFuncSetAttribute(gemm_h<false, false>, cudaFuncAttributeMaxDynamicSharedMemorySize, GH_SMEM_BYTES);
    cudaFuncSetAttribute(gemm_h<true,  false>, cudaFuncAttributeMaxDynamicSharedMemorySize, GH_SMEM_BYTES);
    cudaFuncSetAttribute(gemm_h<false, true >, cudaFuncAttributeMaxDynamicSharedMemorySize, GH_SMEM_BYTES);
    cudaFuncSetAttribute(gemm_kvq, cudaFuncAttributeMaxDynamicSharedMemorySize, GH_SMEM_BYTES);
    cudaFuncSetAttribute(flash_attn, cudaFuncAttributeMaxDynamicSharedMemorySize, FL_SMEM_BYTES);

    // merged prologue + transpose (1 launch)
    {
        PrepArgs pa;
        const int base[5] = {2, 7, 12, 17, 22};
        for (int s = 0; s < 5; s++) {
            pa.g[s] = (const float*)d_in[base[s] + 0];
            pa.b[s] = (const float*)d_in[base[s] + 1];
            pa.m[s] = (const float*)d_in[base[s] + 2];
            pa.v[s] = (const float*)d_in[base[s] + 3];
        }
        pa.wsrc[0] = kv_w;  pa.wdst[0] = kvw;  pa.wn[0] = KVC * CIN;
        pa.wsrc[1] = q_w;   pa.wdst[1] = qw;   pa.wn[1] = QC * CIN;
        pa.wsrc[2] = mg_w;  pa.wdst[2] = mgw;  pa.wn[2] = DOUT * MERGE;
        pa.wsrc[3] = fc1_w; pa.wdst[3] = fc1w; pa.wn[3] = HID * DOUT;
        pa.wsrc[4] = fc2_w; pa.wdst[4] = fc2w; pa.wn[4] = DOUT * HID;
        pa.qmul = (float)(0.17677669529663687 * 1.4426950408889634);
        int wtotal = pa.wn[0] + pa.wn[1] + pa.wn[2] + pa.wn[3] + pa.wn[4];
        int nblk = 8206 + (wtotal + 255) / 256;
        prep_trans<<<nblk, 256>>>(pa, sc, bi, x, xT, xqT);
    }

    // kv + q in one launch (q rides the wave tail)
    gemm_kvq<<<dim3(10, 9, BATCH), 256, GH_SMEM_BYTES>>>(
        xT, kvw, kv, xqT, qw, q, sc, bi);

    // fused attention -> oT
    flash_attn<<<dim3(QP / 128, BATCH * HEADS), 256, FL_SMEM_BYTES>>>(q, kv, oT);

    // mg = f16(BN(oT @ mg_w^T))
    gemm_h<false, false>
        <<<dim3(DOUT / 128, QP / 128, BATCH), 256, GH_SMEM_BYTES>>>(
            oT, mgw, mg, MERGE, DOUT,
            (long long)QP * MERGE, (long long)QP * DOUT, sc + 1536, bi + 1536);

    // f1 = f16(gelu(BN(mg @ fc1_w^T)))
    gemm_h<true, false>
        <<<dim3(HID / 128, QP / 128, BATCH), 256, GH_SMEM_BYTES>>>(
            mg, fc1w, f1, DOUT, HID,
            (long long)QP * DOUT, (long long)QP * HID, sc + 2048, bi + 2048);

    // out = BN(f1 @ fc2_w^T)^T  f32
    gemm_h<false, true>
        <<<dim3(DOUT / 128, QP / 128, BATCH), 256, GH_SMEM_BYTES>>>(
            f1, fc2w, out, HID, QP,
            (long long)QP * HID, (long long)DOUT * QP, sc + 3072, bi + 3072);
}

// round 16
// speedup vs baseline: 1.5421x; 1.5421x over previous
#include <cuda_runtime.h>
#include <cuda_fp16.h>
#include <math.h>
#include <stdint.h>

// ---------------------------------------------------------------------------
// SubSample attention block — fp16 mma.sync (m16n8k16), position-major.
// Round 16: byte-identical resubmit of round 15 (coalesced fc2 TRANS epilogue
// + merged prep/xtrans). Round 15's 449us ruled environmental: the UNTOUCHED
// mg GEMM ran 2x slower with identical pipe mix (DVFS throttle signature).
// ---------------------------------------------------------------------------

constexpr int BATCH = 32, CIN = 256, NP = 1024, QP = 256;
constexpr int HEADS = 8, KD = 32, VD = 128;
constexpr int KVC = (KD + VD) * HEADS;   // 1280
constexpr int QC  = HEADS * KD;          // 256
constexpr int MERGE = HEADS * VD;        // 1024
constexpr int DOUT = 512, HID = 1024;

constexpr int HS_STAGE = 128 * 72;                 // halves per operand-stage
constexpr int GH_SMEM_BYTES = 4 * HS_STAGE * 2;    // 73728

constexpr int FL_QS = 128 * 40;
constexpr int FL_KS = 128 * 40;
constexpr int FL_VS = 128 * 136;
constexpr int FL_SMEM_BYTES = (FL_QS + 2 * FL_KS + 2 * FL_VS) * 2;  // 100352

__device__ __align__(16) __half g_x16T [(size_t)BATCH * NP * CIN];
__device__ __align__(16) __half g_xq16T[(size_t)BATCH * QP * CIN];
__device__ __align__(16) __half g_kv16 [(size_t)BATCH * NP * KVC];
__device__ __align__(16) __half g_q16  [(size_t)BATCH * QP * QC];
__device__ __align__(16) __half g_oT16 [(size_t)BATCH * QP * MERGE];
__device__ __align__(16) __half g_mg16 [(size_t)BATCH * QP * DOUT];
__device__ __align__(16) __half g_f116 [(size_t)BATCH * QP * HID];
__device__ __align__(16) __half g_kvw16 [KVC * CIN];
__device__ __align__(16) __half g_qw16  [QC * CIN];
__device__ __align__(16) __half g_mgw16 [DOUT * MERGE];
__device__ __align__(16) __half g_fc1w16[HID * DOUT];
__device__ __align__(16) __half g_fc2w16[DOUT * HID];
__device__ float g_sc[3584];
__device__ float g_bi[3584];

__device__ __forceinline__ float gelu_exact(float x) {
    return 0.5f * x * (1.0f + erff(x * 0.70710678118654752f));
}

__device__ __forceinline__ void cpa16(void* dst, const void* src) {
    unsigned d = (unsigned)__cvta_generic_to_shared(dst);
    asm volatile("cp.async.ca.shared.global [%0], [%1], 16;\n" :: "r"(d), "l"(src));
}
__device__ __forceinline__ void cp_commit() { asm volatile("cp.async.commit_group;\n"); }
template <int W> __device__ __forceinline__ void cp_wait() {
    asm volatile("cp.async.wait_group %0;\n" :: "n"(W));
}

__device__ __forceinline__ void mma_f16(float* c, const unsigned* a, unsigned b0, unsigned b1) {
    asm volatile(
        "mma.sync.aligned.m16n8k16.row.col.f32.f16.f16.f32 "
        "{%0,%1,%2,%3}, {%4,%5,%6,%7}, {%8,%9}, {%0,%1,%2,%3};"
        : "+f"(c[0]), "+f"(c[1]), "+f"(c[2]), "+f"(c[3])
        : "r"(a[0]), "r"(a[1]), "r"(a[2]), "r"(a[3]), "r"(b0), "r"(b1));
}

__device__ __forceinline__ void ldsm4(unsigned& r0, unsigned& r1, unsigned& r2,
                                      unsigned& r3, unsigned addr) {
    asm volatile("ldmatrix.sync.aligned.m8n8.x4.shared.b16 {%0,%1,%2,%3}, [%4];"
                 : "=r"(r0), "=r"(r1), "=r"(r2), "=r"(r3) : "r"(addr));
}
__device__ __forceinline__ void ldsm_t4(unsigned& r0, unsigned& r1, unsigned& r2,
                                        unsigned& r3, unsigned addr) {
    asm volatile("ldmatrix.sync.aligned.m8n8.x4.trans.shared.b16 {%0,%1,%2,%3}, [%4];"
                 : "=r"(r0), "=r"(r1), "=r"(r2), "=r"(r3) : "r"(addr));
}

__device__ __forceinline__ unsigned packh2(float a, float b) {
    __half2 h = __floats2half2_rn(a, b);
    return *reinterpret_cast<unsigned*>(&h);
}
__device__ __forceinline__ unsigned ldu32(const __half* p) {
    return *reinterpret_cast<const unsigned*>(p);
}
__device__ __forceinline__ unsigned s2u32(const void* p) {
    unsigned a;
    asm("{ .reg .u64 tmp; cvta.to.shared.u64 tmp, %1; cvt.u32.u64 %0, tmp; }"
        : "=r"(a) : "l"(p));
    return a;
}

// ---------------------------------------------------------------------------
// merged prologue + transpose: blocks [0,8192) transpose x; [8192,8206) fold
// BN; [8206,...) convert weights. All parts independent.
// ---------------------------------------------------------------------------
struct PrepArgs {
    const float *g[5], *b[5], *m[5], *v[5];
    const float* wsrc[5];
    __half* wdst[5];
    int wn[5];
    float qmul;
};
__global__ void prep_trans(PrepArgs pa, float* __restrict__ sc, float* __restrict__ bi,
                           const float* __restrict__ x, __half* __restrict__ xT,
                           __half* __restrict__ xqT) {
    __shared__ float tile[32][33];
    const int bid = blockIdx.x;
    const int t = threadIdx.x;
    if (bid < 8192) {
        int bxx = bid & 31;
        int byy = (bid >> 5) & 7;
        int bz  = bid >> 8;
        int tx = t & 31, ty = t >> 5;
        int hw0 = bxx * 32, c0 = byy * 32;
#pragma unroll
        for (int j = 0; j < 4; j++)
            tile[ty + 8 * j][tx] =
                x[((size_t)(bz * CIN + c0 + ty + 8 * j) << 10) + hw0 + tx];
        __syncthreads();
        const bool evenrow = (bxx & 1) == 0;
#pragma unroll
        for (int j = 0; j < 4; j++) {
            int hwl = ty + 8 * j;
            __half v = __float2half_rn(tile[tx][hwl]);
            xT[((size_t)bz * NP + hw0 + hwl) * CIN + c0 + tx] = v;
            if (evenrow && !(hwl & 1)) {
                int qp = (bxx >> 1) * 16 + (hwl >> 1);
                xqT[((size_t)bz * QP + qp) * CIN + c0 + tx] = v;
            }
        }
        return;
    }
    if (bid < 8206) {
        int i = (bid - 8192) * 256 + t;
        if (i >= 3584) return;
        int seg, off;
        float mul = 1.0f;
        if (i < 1280)      { seg = 0; off = 0; }
        else if (i < 1536) { seg = 1; off = 1280; mul = pa.qmul; }
        else if (i < 2048) { seg = 2; off = 1536; }
        else if (i < 3072) { seg = 3; off = 2048; }
        else               { seg = 4; off = 3072; }
        int j = i - off;
        float s = pa.g[seg][j] * rsqrtf(pa.v[seg][j] + 1e-5f);
        sc[i] = s * mul;
        bi[i] = (pa.b[seg][j] - pa.m[seg][j] * s) * mul;
        return;
    }
    int i = (bid - 8206) * 256 + t;
#pragma unroll
    for (int s = 0; s < 5; s++) {
        if (i < pa.wn[s]) { pa.wdst[s][i] = __float2half_rn(pa.wsrc[s][i]); return; }
        i -= pa.wn[s];
    }
}

// ---------------------------------------------------------------------------
// fp16 GEMM core: BK=64, 2-stage cp.async, ldmatrix fragments.
// TRANS epilogue: transposed smem bounce [n][136] -> coalesced f32 row stores.
// ---------------------------------------------------------------------------
template <bool GEL, bool TRANS>
__device__ __forceinline__
void gemm_core(const __half* __restrict__ Abase, const __half* __restrict__ Bbase,
               void* __restrict__ Cv, int K, int ldc, int bm, int bn,
               const float* __restrict__ scale, const float* __restrict__ bias,
               __half* smh) {
    __half* As = smh;                    // [2][128*72]
    __half* Bs = smh + 2 * HS_STAGE;     // [2][128*72]

    const int t = threadIdx.x, warp = t >> 5, lane = t & 31;
    const int wm = warp & 1, wn = warp >> 1;
    const int g = lane >> 2, tq = lane & 3;

    const __half* Ab = Abase + (long long)bm * K;
    const __half* Bb = Bbase + (long long)bn * K;

    const int arow = ((lane >> 3) & 1) * 8 + (lane & 7);
    const int akadd = (lane >> 4) * 8;
    const int brow = (lane >> 4) * 8 + (lane & 7);
    const int bkadd = ((lane >> 3) & 1) * 8;
    const unsigned as_u32 = s2u32(As);
    const unsigned bs_u32 = s2u32(Bs);

    auto ldtile = [&](int s, int k0) {
#pragma unroll
        for (int j = 0; j < 4; j++) {
            int idx = j * 256 + t;
            int r = idx >> 3, c = idx & 7;
            cpa16(As + s * HS_STAGE + r * 72 + c * 8, Ab + (long long)r * K + k0 + c * 8);
            cpa16(Bs + s * HS_STAGE + r * 72 + c * 8, Bb + (long long)r * K + k0 + c * 8);
        }
    };

    float acc[4][4][4];
#pragma unroll
    for (int i = 0; i < 4; i++)
#pragma unroll
        for (int j = 0; j < 4; j++)
#pragma unroll
            for (int r = 0; r < 4; r++) acc[i][j][r] = 0.0f;

    const int niter = K >> 6;
    ldtile(0, 0);
    cp_commit();

    for (int it = 0; it < niter; it++) {
        const int s = it & 1;
        if (it + 1 < niter) ldtile(s ^ 1, (it + 1) << 6);
        cp_commit();
        cp_wait<1>();
        __syncthreads();

        const unsigned as0 = as_u32 + (unsigned)(s * HS_STAGE * 2);
        const unsigned bs0 = bs_u32 + (unsigned)(s * HS_STAGE * 2);
#pragma unroll
        for (int kb = 0; kb < 4; kb++) {
            const int ko = kb * 16;
            unsigned a[4][4];
#pragma unroll
            for (int mi = 0; mi < 4; mi++)
                ldsm4(a[mi][0], a[mi][1], a[mi][2], a[mi][3],
                      as0 + 2u * (unsigned)((wm * 64 + mi * 16 + arow) * 72 + ko + akadd));
            unsigned b[4][2];
#pragma unroll
            for (int nip = 0; nip < 2; nip++)
                ldsm4(b[2 * nip][0], b[2 * nip][1], b[2 * nip + 1][0], b[2 * nip + 1][1],
                      bs0 + 2u * (unsigned)((wn * 32 + nip * 16 + brow) * 72 + ko + bkadd));
#pragma unroll
            for (int mi = 0; mi < 4; mi++)
#pragma unroll
                for (int ni = 0; ni < 4; ni++)
                    mma_f16(acc[mi][ni], a[mi], b[ni][0], b[ni][1]);
        }
        __syncthreads();
    }

    if (!TRANS) {
        __half* Cb = reinterpret_cast<__half*>(Cv);
#pragma unroll
        for (int mi = 0; mi < 4; mi++) {
            int r0 = bm + wm * 64 + mi * 16 + g;
            int r1 = r0 + 8;
#pragma unroll
            for (int ni = 0; ni < 4; ni++) {
                int col = bn + wn * 32 + ni * 8 + 2 * tq;
                float s0 = scale[col], b0s = bias[col];
                float s1 = scale[col + 1], b1s = bias[col + 1];
                float v0 = fmaf(acc[mi][ni][0], s0, b0s);
                float v1 = fmaf(acc[mi][ni][1], s1, b1s);
                float v2 = fmaf(acc[mi][ni][2], s0, b0s);
                float v3 = fmaf(acc[mi][ni][3], s1, b1s);
                if (GEL) {
                    v0 = gelu_exact(v0); v1 = gelu_exact(v1);
                    v2 = gelu_exact(v2); v3 = gelu_exact(v3);
                }
                *reinterpret_cast<unsigned*>(Cb + (long long)r0 * ldc + col) = packh2(v0, v1);
                *reinterpret_cast<unsigned*>(Cb + (long long)r1 * ldc + col) = packh2(v2, v3);
            }
        }
    } else {
        float* Cs = reinterpret_cast<float*>(smh);   // [128 n][136]
        __syncthreads();
#pragma unroll
        for (int mi = 0; mi < 4; mi++) {
            int r0 = wm * 64 + mi * 16 + g;
            int r1 = r0 + 8;
#pragma unroll
            for (int ni = 0; ni < 4; ni++) {
                int col = wn * 32 + ni * 8 + 2 * tq;
                int cg = bn + col;
                float s0 = scale[cg], b0s = bias[cg];
                float s1 = scale[cg + 1], b1s = bias[cg + 1];
                Cs[col * 136 + r0]       = fmaf(acc[mi][ni][0], s0, b0s);
                Cs[(col + 1) * 136 + r0] = fmaf(acc[mi][ni][1], s1, b1s);
                Cs[col * 136 + r1]       = fmaf(acc[mi][ni][2], s0, b0s);
                Cs[(col + 1) * 136 + r1] = fmaf(acc[mi][ni][3], s1, b1s);
            }
        }
        __syncthreads();
        float* Cb = reinterpret_cast<float*>(Cv);
#pragma unroll
        for (int i = 0; i < 16; i++) {
            int idx = i * 256 + t;
            int n = idx >> 5;
            int m = (idx & 31) * 4;
            float4 v = *reinterpret_cast<const float4*>(Cs + n * 136 + m);
            *reinterpret_cast<float4*>(Cb + (long long)(bn + n) * ldc + bm + m) = v;
        }
    }
}

// generic single-GEMM wrapper
template <bool GEL, bool TRANS>
__global__ __launch_bounds__(256, 2)
void gemm_h(const __half* __restrict__ A, const __half* __restrict__ B,
            void* __restrict__ Cv,
            int K, int ldc, long long sA, long long sC,
            const float* __restrict__ scale, const float* __restrict__ bias) {
    extern __shared__ __half smh[];
    const __half* Az = A + (long long)blockIdx.z * sA;
    char* Cz = reinterpret_cast<char*>(Cv) +
               (long long)blockIdx.z * sC * (TRANS ? 4 : 2);
    gemm_core<GEL, TRANS>(Az, B, Cz, K, ldc,
                          blockIdx.y * 128, blockIdx.x * 128, scale, bias, smh);
}

// fused kv + q wrapper: grid (10, 9, 32). y<8 -> kv tile; y==8, x<4 -> q tile.
__global__ __launch_bounds__(256, 2)
void gemm_kvq(const __half* __restrict__ xT, const __half* __restrict__ kvw,
              __half* __restrict__ kv,
              const __half* __restrict__ xqT, const __half* __restrict__ qw,
              __half* __restrict__ qo,
              const float* __restrict__ sc, const float* __restrict__ bi) {
    extern __shared__ __half smh[];
    const int z = blockIdx.z;
    if (blockIdx.y < 8) {
        gemm_core<false, false>(xT + (long long)z * NP * CIN, kvw,
                                kv + (long long)z * NP * KVC,
                                CIN, KVC, blockIdx.y * 128, blockIdx.x * 128,
                                sc + 0, bi + 0, smh);
    } else {
        if (blockIdx.x >= 4) return;
        const int qm = blockIdx.x >> 1, qn = blockIdx.x & 1;
        gemm_core<false, false>(xqT + (long long)z * QP * CIN, qw,
                                qo + (long long)z * QP * QC,
                                CIN, QC, qm * 128, qn * 128,
                                sc + 1280, bi + 1280, smh);
    }
}

// ---------------------------------------------------------------------------
// Flash attention fp16, 128-key blocks, exp2-domain softmax.
// ---------------------------------------------------------------------------
__global__ __launch_bounds__(256, 1)
void flash_attn(const __half* __restrict__ q, const __half* __restrict__ kv,
                __half* __restrict__ oT) {
    const int t    = threadIdx.x;
    const int warp = t >> 5, lane = t & 31;
    const int g    = lane >> 2, tq = lane & 3;
    const int bh   = blockIdx.y;
    const int b    = bh >> 3, h = bh & 7;
    const int q0   = blockIdx.x * 128;

    extern __shared__ __half smh[];
    __half* Qs = smh;               // [128 qp][40]
    __half* Ks = Qs + FL_QS;        // [2][128 n][40]
    __half* Vs = Ks + 2 * FL_KS;    // [2][128 n][136]

    const __half* kvb = kv + (size_t)b * NP * KVC + h * (KD + VD);

    auto loadKV = [&](int s, int n0) {
        __half* ks = Ks + s * FL_KS;
#pragma unroll
        for (int j = 0; j < 2; j++) {
            int idx = j * 256 + t;
            int n = idx >> 2, c = idx & 3;
            cpa16(ks + n * 40 + c * 8, kvb + (size_t)(n0 + n) * KVC + c * 8);
        }
        __half* vs = Vs + s * FL_VS;
#pragma unroll
        for (int j = 0; j < 8; j++) {
            int idx = j * 256 + t;
            int n = idx >> 4, c = idx & 15;
            cpa16(vs + n * 136 + c * 8, kvb + (size_t)(n0 + n) * KVC + KD + c * 8);
        }
    };

#pragma unroll
    for (int j = 0; j < 2; j++) {
        int idx = j * 256 + t;
        int r = idx >> 2, c = idx & 3;
        cpa16(Qs + r * 40 + c * 8, q + ((size_t)b * QP + q0 + r) * QC + h * KD + c * 8);
    }
    loadKV(0, 0);
    cp_commit();

    unsigned aq[2][4];
    float m0 = -1e30f, m1 = -1e30f, l0 = 0.0f, l1 = 0.0f;
    float o[16][4];
#pragma unroll
    for (int j = 0; j < 16; j++)
#pragma unroll
        for (int r = 0; r < 4; r++) o[j][r] = 0.0f;

    const int brow = (lane >> 4) * 8 + (lane & 7);
    const int bkadd = ((lane >> 3) & 1) * 8;
    const int lmi = lane >> 3, lrow = lane & 7;
    const int ldrow = ((lmi & 1) * 8 + lrow) * 136 + (lmi >> 1) * 8;

    for (int blk = 0; blk < 8; blk++) {
        const int s = blk & 1;
        if (blk + 1 < 8) loadKV(s ^ 1, (blk + 1) * 128);
        cp_commit();
        cp_wait<1>();
        __syncthreads();

        if (blk == 0) {
#pragma unroll
            for (int kb = 0; kb < 2; kb++) {
                int r = warp * 16 + g;
                aq[kb][0] = ldu32(Qs + r * 40 + kb * 16 + 2 * tq);
                aq[kb][1] = ldu32(Qs + (r + 8) * 40 + kb * 16 + 2 * tq);
                aq[kb][2] = ldu32(Qs + r * 40 + kb * 16 + 2 * tq + 8);
                aq[kb][3] = ldu32(Qs + (r + 8) * 40 + kb * 16 + 2 * tq + 8);
            }
        }

        const unsigned ks_u32 = s2u32(Ks + s * FL_KS);
        const unsigned vs_u32 = s2u32(Vs + s * FL_VS);

        float p[16][4];
#pragma unroll
        for (int ni = 0; ni < 16; ni++)
            p[ni][0] = p[ni][1] = p[ni][2] = p[ni][3] = 0.0f;
#pragma unroll
        for (int kb = 0; kb < 2; kb++) {
#pragma unroll
            for (int nip = 0; nip < 8; nip++) {
                unsigned b00, b01, b10, b11;
                ldsm4(b00, b01, b10, b11,
                      ks_u32 + 2u * (unsigned)((nip * 16 + brow) * 40 + kb * 16 + bkadd));
                mma_f16(p[2 * nip],     aq[kb], b00, b01);
                mma_f16(p[2 * nip + 1], aq[kb], b10, b11);
            }
        }

        float bm0 = -1e30f, bm1 = -1e30f;
#pragma unroll
        for (int ni = 0; ni < 16; ni++) {
            bm0 = fmaxf(bm0, fmaxf(p[ni][0], p[ni][1]));
            bm1 = fmaxf(bm1, fmaxf(p[ni][2], p[ni][3]));
        }
        bm0 = fmaxf(bm0, __shfl_xor_sync(0xffffffffu, bm0, 1));
        bm0 = fmaxf(bm0, __shfl_xor_sync(0xffffffffu, bm0, 2));
        bm1 = fmaxf(bm1, __shfl_xor_sync(0xffffffffu, bm1, 1));
        bm1 = fmaxf(bm1, __shfl_xor_sync(0xffffffffu, bm1, 2));
        float mn0 = fmaxf(m0, bm0), mn1 = fmaxf(m1, bm1);
        float al0 = exp2f(m0 - mn0), al1 = exp2f(m1 - mn1);
        float rs0 = 0.0f, rs1 = 0.0f;
#pragma unroll
        for (int ni = 0; ni < 16; ni++) {
            p[ni][0] = exp2f(p[ni][0] - mn0);
            p[ni][1] = exp2f(p[ni][1] - mn0);
            p[ni][2] = exp2f(p[ni][2] - mn1);
            p[ni][3] = exp2f(p[ni][3] - mn1);
            rs0 += p[ni][0] + p[ni][1];
            rs1 += p[ni][2] + p[ni][3];
        }
        rs0 += __shfl_xor_sync(0xffffffffu, rs0, 1);
        rs0 += __shfl_xor_sync(0xffffffffu, rs0, 2);
        rs1 += __shfl_xor_sync(0xffffffffu, rs1, 1);
        rs1 += __shfl_xor_sync(0xffffffffu, rs1, 2);
        l0 = l0 * al0 + rs0;
        l1 = l1 * al1 + rs1;
        m0 = mn0; m1 = mn1;
#pragma unroll
        for (int j = 0; j < 16; j++) {
            o[j][0] *= al0; o[j][1] *= al0;
            o[j][2] *= al1; o[j][3] *= al1;
        }

#pragma unroll
        for (int ki = 0; ki < 8; ki++) {
            unsigned ap[4];
            ap[0] = packh2(p[2 * ki][0],     p[2 * ki][1]);
            ap[1] = packh2(p[2 * ki][2],     p[2 * ki][3]);
            ap[2] = packh2(p[2 * ki + 1][0], p[2 * ki + 1][1]);
            ap[3] = packh2(p[2 * ki + 1][2], p[2 * ki + 1][3]);
#pragma unroll
            for (int jj = 0; jj < 8; jj++) {
                unsigned r0, r1, r2, r3;
                ldsm_t4(r0, r1, r2, r3,
                        vs_u32 + 2u * (unsigned)(ki * 16 * 136 + jj * 16 + ldrow));
                mma_f16(o[2 * jj],     ap, r0, r1);
                mma_f16(o[2 * jj + 1], ap, r2, r3);
            }
        }
        __syncthreads();
    }

    float inv0 = 1.0f / l0, inv1 = 1.0f / l1;
    int r0 = q0 + warp * 16 + g;
    int r1 = r0 + 8;
    __half* orow0 = oT + ((size_t)b * QP + r0) * MERGE + h * VD;
    __half* orow1 = oT + ((size_t)b * QP + r1) * MERGE + h * VD;
#pragma unroll
    for (int j = 0; j < 16; j++) {
        int col = j * 8 + 2 * tq;
        float v0 = gelu_exact(o[j][0] * inv0);
        float v1 = gelu_exact(o[j][1] * inv0);
        float v2 = gelu_exact(o[j][2] * inv1);
        float v3 = gelu_exact(o[j][3] * inv1);
        *reinterpret_cast<unsigned*>(orow0 + col) = packh2(v0, v1);
        *reinterpret_cast<unsigned*>(orow1 + col) = packh2(v2, v3);
    }
}

// ---------------------------------------------------------------------------
extern "C" void kernel_launch(void* const* d_in, const int* in_sizes, int n_in,
                              void* d_out, int out_size) {
    const float* x     = (const float*)d_in[0];
    const float* kv_w  = (const float*)d_in[1];
    const float* q_w   = (const float*)d_in[6];
    const float* mg_w  = (const float*)d_in[11];
    const float* fc1_w = (const float*)d_in[16];
    const float* fc2_w = (const float*)d_in[21];
    float* out = (float*)d_out;

    __half *xT, *xqT, *kv, *q, *oT, *mg, *f1;
    __half *kvw, *qw, *mgw, *fc1w, *fc2w;
    float *sc, *bi;
    cudaGetSymbolAddress((void**)&xT,   g_x16T);
    cudaGetSymbolAddress((void**)&xqT,  g_xq16T);
    cudaGetSymbolAddress((void**)&kv,   g_kv16);
    cudaGetSymbolAddress((void**)&q,    g_q16);
    cudaGetSymbolAddress((void**)&oT,   g_oT16);
    cudaGetSymbolAddress((void**)&mg,   g_mg16);
    cudaGetSymbolAddress((void**)&f1,   g_f116);
    cudaGetSymbolAddress((void**)&kvw,  g_kvw16);
    cudaGetSymbolAddress((void**)&qw,   g_qw16);
    cudaGetSymbolAddress((void**)&mgw,  g_mgw16);
    cudaGetSymbolAddress((void**)&fc1w, g_fc1w16);
    cudaGetSymbolAddress((void**)&fc2w, g_fc2w16);
    cudaGetSymbolAddress((void**)&sc,   g_sc);
    cudaGetSymbolAddress((void**)&bi,   g_bi);

    cudaFuncSetAttribute(gemm_h<false, false>, cudaFuncAttributeMaxDynamicSharedMemorySize, GH_SMEM_BYTES);
    cudaFuncSetAttribute(gemm_h<true,  false>, cudaFuncAttributeMaxDynamicSharedMemorySize, GH_SMEM_BYTES);
    cudaFuncSetAttribute(gemm_h<false, true >, cudaFuncAttributeMaxDynamicSharedMemorySize, GH_SMEM_BYTES);
    cudaFuncSetAttribute(gemm_kvq, cudaFuncAttributeMaxDynamicSharedMemorySize, GH_SMEM_BYTES);
    cudaFuncSetAttribute(flash_attn, cudaFuncAttributeMaxDynamicSharedMemorySize, FL_SMEM_BYTES);

    // merged prologue + transpose (1 launch)
    {
        PrepArgs pa;
        const int base[5] = {2, 7, 12, 17, 22};
        for (int s = 0; s < 5; s++) {
            pa.g[s] = (const float*)d_in[base[s] + 0];
            pa.b[s] = (const float*)d_in[base[s] + 1];
            pa.m[s] = (const float*)d_in[base[s] + 2];
            pa.v[s] = (const float*)d_in[base[s] + 3];
        }
        pa.wsrc[0] = kv_w;  pa.wdst[0] = kvw;  pa.wn[0] = KVC * CIN;
        pa.wsrc[1] = q_w;   pa.wdst[1] = qw;   pa.wn[1] = QC * CIN;
        pa.wsrc[2] = mg_w;  pa.wdst[2] = mgw;  pa.wn[2] = DOUT * MERGE;
        pa.wsrc[3] = fc1_w; pa.wdst[3] = fc1w; pa.wn[3] = HID * DOUT;
        pa.wsrc[4] = fc2_w; pa.wdst[4] = fc2w; pa.wn[4] = DOUT * HID;
        pa.qmul = (float)(0.17677669529663687 * 1.4426950408889634);
        int wtotal = pa.wn[0] + pa.wn[1] + pa.wn[2] + pa.wn[3] + pa.wn[4];
        int nblk = 8206 + (wtotal + 255) / 256;
        prep_trans<<<nblk, 256>>>(pa, sc, bi, x, xT, xqT);
    }

    // kv + q in one launch (q rides the wave tail)
    gemm_kvq<<<dim3(10, 9, BATCH), 256, GH_SMEM_BYTES>>>(
        xT, kvw, kv, xqT, qw, q, sc, bi);

    // fused attention -> oT
    flash_attn<<<dim3(QP / 128, BATCH * HEADS), 256, FL_SMEM_BYTES>>>(q, kv, oT);

    // mg = f16(BN(oT @ mg_w^T))
    gemm_h<false, false>
        <<<dim3(DOUT / 128, QP / 128, BATCH), 256, GH_SMEM_BYTES>>>(
            oT, mgw, mg, MERGE, DOUT,
            (long long)QP * MERGE, (long long)QP * DOUT, sc + 1536, bi + 1536);

    // f1 = f16(gelu(BN(mg @ fc1_w^T)))
    gemm_h<true, false>
        <<<dim3(HID / 128, QP / 128, BATCH), 256, GH_SMEM_BYTES>>>(
            mg, fc1w, f1, DOUT, HID,
            (long long)QP * DOUT, (long long)QP * HID, sc + 2048, bi + 2048);

    // out = BN(f1 @ fc2_w^T)^T  f32
    gemm_h<false, true>
        <<<dim3(DOUT / 128, QP / 128, BATCH), 256, GH_SMEM_BYTES>>>(
            f1, fc2w, out, HID, QP,
            (long long)QP * HID, (long long)DOUT * QP, sc + 3072, bi + 3072);
}